// round 7
// baseline (speedup 1.0000x reference)
#include <cuda_runtime.h>
#include <math.h>

#define HH 512
#define WW 512
#define NB 32
#define MS 10
#define SH 21            // 2*MS+1
#define NS 441           // SH*SH
#define NPIX (HH*WW)     // 262144
#define KAREA (492.0*492.0)
#define EPS 1e-8

#define TB 8                     // image rows per correlation band
#define NBAND (HH/TB)            // 64
#define TROWS (TB + 20)          // 28
#define TSTR 536                 // template row stride (fp32), 16B-aligned, cols 0..531 + 4 pad
#define ISTR 516                 // image row stride (fp32), cols 0..511 + 4 pad
#define CORR_THREADS 336         // 21 p  x  (8 rows x 2 x-halves)
#define SMEM_CORR (TROWS*TSTR*4 + TB*ISTR*4)   // 60032 + 16512 = 76544
#define SMEM_STATS (40*512*4)

// ---------------- scratch ----------------
__device__ double g_tstats[2];
__device__ double g_isum[NB];
__device__ double g_colF1[NB*WW];
__device__ double g_colF2[NB*WW];
__device__ float  g_den[NB*NS];
__device__ float  g_ccpart[NB*NBAND*NS];
__device__ float  g_shift[NB*2];

// ---------------- K0: zero atomic targets ----------------
__global__ void k_zero() {
    int i = blockIdx.x * blockDim.x + threadIdx.x;
    if (i < NB * WW) { g_colF1[i] = 0.0; g_colF2[i] = 0.0; }
    if (i < 2) g_tstats[i] = 0.0;
}

// ---------------- K1: column partial sums + template stats ----------------
__global__ void k_colpart(const float* __restrict__ fr, const float* __restrict__ tp) {
    int b = blockIdx.x;
    int slab = blockIdx.y;
    int x = threadIdx.x;
    const float* src = (b < NB) ? (fr + (size_t)b * NPIX) : tp;
    int y0 = slab * 64;
    float s1a = 0.f, s1b = 0.f, s2a = 0.f, s2b = 0.f;
#pragma unroll 4
    for (int y = y0; y < y0 + 64; y += 2) {
        float v0 = src[y * WW + x];
        float v1 = src[(y + 1) * WW + x];
        s1a += v0; s1b += v1;
        s2a = fmaf(v0, v0, s2a); s2b = fmaf(v1, v1, s2b);
    }
    double d1 = (double)s1a + (double)s1b;
    double d2 = (double)s2a + (double)s2b;
    if (b < NB) {
        atomicAdd(&g_colF1[b * WW + x], d1);
        atomicAdd(&g_colF2[b * WW + x], d2);
    } else {
        __shared__ double r1[512], r2[512];
        r1[x] = d1; r2[x] = d2;
        __syncthreads();
        for (int st = 256; st > 0; st >>= 1) {
            if (x < st) { r1[x] += r1[x + st]; r2[x] += r2[x + st]; }
            __syncthreads();
        }
        if (x == 0) {
            atomicAdd(&g_tstats[0], r1[0]);
            atomicAdd(&g_tstats[1], r2[0]);
        }
    }
}

// ---------------- K2: all 441 window denominators per frame ----------------
__global__ void k_stats(const float* __restrict__ fr) {
    __shared__ double scol1[512], scol2[512];
    __shared__ double srow1[40], srow2[40];
    __shared__ double rowPre1[41], rowPre2[41];
    __shared__ double colPre1[21], colPre2[21];
    __shared__ double colSuf1[21], colSuf2[21];
    __shared__ double spart1[16], spart2[16];
    __shared__ double sS1s, sS2s;
    __shared__ float PP1[41*41], PP2[41*41];
    extern __shared__ float sedge[];         // 40*512

    int b = blockIdx.x, tid = threadIdx.x;   // 512 threads
    scol1[tid] = g_colF1[b * WW + tid];
    scol2[tid] = g_colF2[b * WW + tid];
    const float* im = fr + (size_t)b * NPIX;
    for (int idx = tid; idx < 40 * 512; idx += 512) {
        int r = idx >> 9, c = idx & 511;
        int y = (r < 20) ? r : (472 + r);
        sedge[idx] = im[y * WW + c];
    }
    __syncthreads();

    int wid = tid >> 5, lane = tid & 31;
    for (int r = wid; r < 40; r += 16) {
        double a = 0.0, c2 = 0.0;
        for (int c = lane; c < 512; c += 32) {
            double v = (double)sedge[r * 512 + c];
            a += v; c2 += v * v;
        }
#pragma unroll
        for (int s = 16; s > 0; s >>= 1) {
            a  += __shfl_down_sync(0xffffffffu, a, s);
            c2 += __shfl_down_sync(0xffffffffu, c2, s);
        }
        if (lane == 0) { srow1[r] = a; srow2[r] = c2; }
    }
    for (int idx = tid; idx < 41 * 41; idx += 512) { PP1[idx] = 0.f; PP2[idx] = 0.f; }
    __syncthreads();

    for (int idx = tid; idx < 1600; idx += 512) {
        int r = idx / 40, cc = idx - r * 40;
        int col = (cc < 20) ? cc : (472 + cc);
        float v = sedge[r * 512 + col];
        PP1[(r + 1) * 41 + cc + 1] = v;
        PP2[(r + 1) * 41 + cc + 1] = v * v;
    }
    {
        double a = scol1[tid], c2 = scol2[tid];
#pragma unroll
        for (int s = 16; s > 0; s >>= 1) {
            a  += __shfl_down_sync(0xffffffffu, a, s);
            c2 += __shfl_down_sync(0xffffffffu, c2, s);
        }
        if (lane == 0) { spart1[wid] = a; spart2[wid] = c2; }
    }
    __syncthreads();

    if (tid < 41) {
        float a = 0.f, c2 = 0.f;
        for (int c = 0; c < 41; ++c) {
            a  += PP1[tid * 41 + c]; PP1[tid * 41 + c] = a;
            c2 += PP2[tid * 41 + c]; PP2[tid * 41 + c] = c2;
        }
    }
    if (tid == 64)  { double a = 0; rowPre1[0] = 0; for (int r = 0; r < 40; ++r) { a += srow1[r]; rowPre1[r+1] = a; } }
    if (tid == 96)  { double a = 0; rowPre2[0] = 0; for (int r = 0; r < 40; ++r) { a += srow2[r]; rowPre2[r+1] = a; } }
    if (tid == 128) { double a = 0; colPre1[0] = 0; for (int c = 0; c < 20; ++c) { a += scol1[c]; colPre1[c+1] = a; } }
    if (tid == 160) { double a = 0; colPre2[0] = 0; for (int c = 0; c < 20; ++c) { a += scol2[c]; colPre2[c+1] = a; } }
    if (tid == 192) { double a = 0; colSuf1[20] = 0; for (int j = 19; j >= 0; --j) { a += scol1[492+j]; colSuf1[j] = a; } }
    if (tid == 224) { double a = 0; colSuf2[20] = 0; for (int j = 19; j >= 0; --j) { a += scol2[492+j]; colSuf2[j] = a; } }
    if (tid == 256) { double a = 0; for (int w = 0; w < 16; ++w) a += spart1[w]; sS1s = a; g_isum[b] = a; }
    if (tid == 288) { double a = 0; for (int w = 0; w < 16; ++w) a += spart2[w]; sS2s = a; }
    __syncthreads();

    if (tid < 41) {
        float a = 0.f, c2 = 0.f;
        for (int r = 0; r < 41; ++r) {
            a  += PP1[r * 41 + tid]; PP1[r * 41 + tid] = a;
            c2 += PP2[r * 41 + tid]; PP2[r * 41 + tid] = c2;
        }
    }
    __syncthreads();

#define RECT(PP, r0, r1, c0, c1) \
    (PP[(r1)*41+(c1)] - PP[(r0)*41+(c1)] - PP[(r1)*41+(c0)] + PP[(r0)*41+(c0)])
    if (tid < NS) {
        int p = tid / SH, j = tid - p * SH;
        double rsum1 = rowPre1[p] + (rowPre1[40] - rowPre1[p + 20]);
        double rsum2 = rowPre2[p] + (rowPre2[40] - rowPre2[p + 20]);
        double csum1 = colPre1[j] + colSuf1[j];
        double csum2 = colPre2[j] + colSuf2[j];
        float q1 = RECT(PP1, 0, p, 0, j) + RECT(PP1, 0, p, 20 + j, 40)
                 + RECT(PP1, p + 20, 40, 0, j) + RECT(PP1, p + 20, 40, 20 + j, 40);
        float q2 = RECT(PP2, 0, p, 0, j) + RECT(PP2, 0, p, 20 + j, 40)
                 + RECT(PP2, p + 20, 40, 0, j) + RECT(PP2, p + 20, 40, 20 + j, 40);
        double w1 = sS1s - rsum1 - csum1 + (double)q1;
        double w2 = sS2s - rsum2 - csum2 + (double)q2;
        double m1 = w1 / KAREA;
        double m2 = w2 / KAREA;
        double var = m2 - m1 * m1 / KAREA + EPS;
        float vf = (float)var;
        if (vf < 0.f) vf = 0.f;
        float tvar = (float)(g_tstats[1] - g_tstats[0] * g_tstats[0] / (double)NPIX + EPS);
        g_den[(size_t)b * NS + tid] = sqrtf(tvar * vf);
    }
#undef RECT
}

// ---------------- K3: the correlation (hot kernel) ----------------
template<int U>
__device__ __forceinline__ void sgstep(const float* __restrict__ tpr,
                                       const float* __restrict__ ip,
                                       float win[24], float acc[SH], float4& cur) {
    const int X = 4 * U;
    float4 nxt = *(const float4*)(ip + X + 4);          // next subgroup's image
    float4 tw  = *(const float4*)(tpr + X + 24);        // window refill T[X+24..X+27]
#pragma unroll
    for (int j = 0; j < SH; ++j) acc[j] = fmaf(cur.x, win[(X + 20 - j) % 24], acc[j]);
#pragma unroll
    for (int j = 0; j < SH; ++j) acc[j] = fmaf(cur.y, win[(X + 21 - j) % 24], acc[j]);
#pragma unroll
    for (int j = 0; j < SH; ++j) acc[j] = fmaf(cur.z, win[(X + 22 - j) % 24], acc[j]);
#pragma unroll
    for (int j = 0; j < SH; ++j) acc[j] = fmaf(cur.w, win[(X + 23 - j) % 24], acc[j]);
    win[(X + 0) % 24] = tw.x;                           // refill dead slots
    win[(X + 1) % 24] = tw.y;
    win[(X + 2) % 24] = tw.z;
    win[(X + 3) % 24] = tw.w;
    cur = nxt;
}

__global__ void __launch_bounds__(CORR_THREADS, 3)
k_corr(const float* __restrict__ fr, const float* __restrict__ tp) {
    int b = blockIdx.x;
    int band = blockIdx.y;
    int y0 = band * TB;
    extern __shared__ float sm[];
    float* sm_t = sm;                       // TROWS x TSTR (fp32)
    float* sm_i = sm + TROWS * TSTR;        // TB x ISTR    (fp32)
    int tid = threadIdx.x;

    for (int idx = tid; idx < TROWS * 532; idx += CORR_THREADS) {
        int r = idx / 532, c = idx - r * 532;
        sm_t[r * TSTR + c] = tp[((y0 - MS + r) & (HH - 1)) * WW + ((c - MS) & (WW - 1))];
    }
    const float* im = fr + (size_t)b * NPIX + (size_t)y0 * WW;
    for (int idx = tid; idx < TB * WW; idx += CORR_THREADS) {
        int r = idx >> 9, c = idx & (WW - 1);
        sm_i[r * ISTR + c] = im[idx];
    }
    // zero pads (image cols 512..515, template cols 532..535)
    if (tid < TB * 4)
        sm_i[(tid >> 2) * ISTR + 512 + (tid & 3)] = 0.f;
    else if (tid >= 64 && tid < 64 + TROWS * 4) {
        int t = tid - 64;
        sm_t[(t >> 2) * TSTR + 532 + (t & 3)] = 0.f;
    }
    __syncthreads();

    int yl = tid & 15;                      // r (0..7) x half (0..1)
    int r  = yl & 7;
    int h  = yl >> 3;
    int p  = tid >> 4;
    const float* tpr = sm_t + (r + 2 * MS - p) * TSTR + h * 256;
    const float* ip  = sm_i + r * ISTR + h * 256;

    float acc[SH];
#pragma unroll
    for (int j = 0; j < SH; ++j) acc[j] = 0.f;

    float win[24];
#pragma unroll
    for (int w = 0; w < 6; ++w) {
        float4 t = *(const float4*)(tpr + 4 * w);
        win[4*w + 0] = t.x; win[4*w + 1] = t.y; win[4*w + 2] = t.z; win[4*w + 3] = t.w;
    }
    float4 cur = *(const float4*)ip;

#pragma unroll 1
    for (int it = 0; it < 10; ++it) {       // 10 x 24 = 240 px
        sgstep<0>(tpr, ip, win, acc, cur);
        sgstep<1>(tpr, ip, win, acc, cur);
        sgstep<2>(tpr, ip, win, acc, cur);
        sgstep<3>(tpr, ip, win, acc, cur);
        sgstep<4>(tpr, ip, win, acc, cur);
        sgstep<5>(tpr, ip, win, acc, cur);
        tpr += 24; ip += 24;
    }
    sgstep<0>(tpr, ip, win, acc, cur);      // px 240..255 (tail reads hit zero pads)
    sgstep<1>(tpr, ip, win, acc, cur);
    sgstep<2>(tpr, ip, win, acc, cur);
    sgstep<3>(tpr, ip, win, acc, cur);
    __syncthreads();

    float* sred = sm;                       // reuse: 441*16 floats
#pragma unroll
    for (int j = 0; j < SH; ++j) sred[(p * SH + j) * 16 + yl] = acc[j];
    __syncthreads();
    for (int s = tid; s < NS; s += CORR_THREADS) {
        float v = 0.f;
#pragma unroll
        for (int k = 0; k < 16; ++k) v += sred[s * 16 + k];
        g_ccpart[((size_t)b * NBAND + band) * NS + s] = v;
    }
}

// ---------------- K4: ncc, argmax, subpixel shift ----------------
__global__ void k_peak() {
    int b = blockIdx.x, tid = threadIdx.x;
    __shared__ float sncc[NS];
    __shared__ float rv[512];
    __shared__ int   ri[512];
    float cfix = (float)(g_isum[b] * g_tstats[0] / (double)NPIX);
    if (tid < NS) {
        float s = 0.f;
        for (int k = 0; k < NBAND; ++k)
            s += g_ccpart[((size_t)b * NBAND + k) * NS + tid];
        float ccv = fabsf(s - cfix);
        float v = ccv / g_den[(size_t)b * NS + tid];
        if (!(v == v)) v = 0.f;
        sncc[tid] = v;
    }
    __syncthreads();
    rv[tid] = (tid < NS) ? sncc[tid] : -1.f;
    ri[tid] = tid;
    __syncthreads();
    for (int st = 256; st > 0; st >>= 1) {
        if (tid < st) {
            float ov = rv[tid + st]; int oi = ri[tid + st];
            if (ov > rv[tid] || (ov == rv[tid] && oi < ri[tid])) { rv[tid] = ov; ri[tid] = oi; }
        }
        __syncthreads();
    }
    if (tid == 0) {
        int am = ri[0];
        int sx = am / SH, sy = am - sx * SH;
        float shx = -(float)(sx - MS);
        float shy = -(float)(sy - MS);
        int xm = sx - 1; if (xm < 0) xm += SH;
        int xp = sx + 1; if (xp > SH - 1) xp = SH - 1;
        int ym = sy - 1; if (ym < 0) ym += SH;
        int yp = sy + 1; if (yp > SH - 1) yp = SH - 1;
        float lxm = logf(sncc[xm * SH + sy]);
        float lxp = logf(sncc[xp * SH + sy]);
        float lym = logf(sncc[sx * SH + ym]);
        float lyp = logf(sncc[sx * SH + yp]);
        float lc4 = 4.f * logf(sncc[sx * SH + sy]);
        shx -= (lxm - lxp) / (2.f * lxm - lc4 + 2.f * lxp);
        shy -= (lym - lyp) / (2.f * lym - lc4 + 2.f * lyp);
        g_shift[b * 2 + 0] = shx;
        g_shift[b * 2 + 1] = shy;
    }
}

// ---------------- K5: bilinear warp + transposed store ----------------
__global__ void k_warp(const float* __restrict__ fr, float* __restrict__ out) {
    int b = blockIdx.z;
    int X0 = blockIdx.x * 32, Y0 = blockIdx.y * 32;
    float dy = g_shift[b * 2 + 0];
    float dx = g_shift[b * 2 + 1];
    __shared__ float sp[36 * 37];
    int ry = Y0 + (int)floorf(-dy) - 1;
    int rx = X0 + (int)floorf(-dx) - 1;
    const float* im = fr + (size_t)b * NPIX;
    for (int idx = threadIdx.x; idx < 36 * 36; idx += 256) {
        int r = idx / 36, c = idx - r * 36;
        int gy = ry + r, gx = rx + c;
        float v = (gy >= 0 && gy < HH && gx >= 0 && gx < WW) ? im[gy * WW + gx] : 0.f;
        sp[r * 37 + c] = v;
    }
    __syncthreads();
    int oy = threadIdx.x & 31;
    int oxb = threadIdx.x >> 5;
    for (int k = 0; k < 4; ++k) {
        int ox = oxb + 8 * k;
        int y = Y0 + oy, x = X0 + ox;
        float yq = (float)y - dy; float y0f = floorf(yq); float wy = yq - y0f;
        float xq = (float)x - dx; float x0f = floorf(xq); float wx = xq - x0f;
        int iy = (int)y0f - ry; int ix = (int)x0f - rx;
        iy = max(0, min(34, iy)); ix = max(0, min(34, ix));
        float v00 = sp[iy * 37 + ix];
        float v01 = sp[iy * 37 + ix + 1];
        float v10 = sp[(iy + 1) * 37 + ix];
        float v11 = sp[(iy + 1) * 37 + ix + 1];
        float val = v00 * (1.f - wy) * (1.f - wx) + v01 * (1.f - wy) * wx
                  + v10 * wy * (1.f - wx) + v11 * wy * wx;
        out[(size_t)b * NPIX + x * HH + y] = val;
    }
}

// ---------------- launch ----------------
extern "C" void kernel_launch(void* const* d_in, const int* in_sizes, int n_in,
                              void* d_out, int out_size) {
    const float* fr = (const float*)d_in[0];
    const float* tp = (const float*)d_in[1];
    if (n_in >= 2 && in_sizes[0] < in_sizes[1]) { const float* t = fr; fr = tp; tp = t; }
    float* out = (float*)d_out;

    cudaFuncSetAttribute(k_corr,  cudaFuncAttributeMaxDynamicSharedMemorySize, SMEM_CORR);
    cudaFuncSetAttribute(k_stats, cudaFuncAttributeMaxDynamicSharedMemorySize, SMEM_STATS);

    k_zero<<<64, 512>>>();
    k_colpart<<<dim3(NB + 1, 8), 512>>>(fr, tp);
    k_stats<<<NB, 512, SMEM_STATS>>>(fr);
    k_corr<<<dim3(NB, NBAND), CORR_THREADS, SMEM_CORR>>>(fr, tp);
    k_peak<<<NB, 512>>>();
    k_warp<<<dim3(16, 16, NB), 256>>>(fr, out);
}

// round 9
// speedup vs baseline: 1.1362x; 1.1362x over previous
#include <cuda_runtime.h>
#include <math.h>

#define HH 512
#define WW 512
#define NB 32
#define MS 10
#define SH 21            // 2*MS+1
#define NS 441           // SH*SH
#define NPIX (HH*WW)     // 262144
#define KAREA (492.0*492.0)
#define EPS 1e-8

#define TB 16                    // rows per correlation band
#define NBAND (HH/TB)            // 32
#define TROWS (TB + 20)          // 36
#define TCOLS (WW + 20)          // 532  (mod 32 = 20 -> conflict-free f4 row access)
#define ISTR 516                 // image row stride (mod 32 = 4 -> conflict-free)
#define CORR_THREADS 336         // 21 p-values x 16 rows
#define SMEM_CORR ((TROWS*TCOLS + TB*ISTR) * 4)   // 109632
#define SMEM_FRONT (40*512*4)

// ---------------- scratch ----------------
__device__ double g_tstats[2];
__device__ double g_isum[NB];
__device__ float  g_den[NB*NS];            // sqrt(window var) only
__device__ float  g_cc[NB*NS];             // accumulated correlations
__device__ float  g_shift[NB*2];

// ---------------- K1: per-frame stats + template stats + zero g_cc ----------------
__global__ void __launch_bounds__(512) k_front(const float* __restrict__ fr,
                                               const float* __restrict__ tp) {
    __shared__ double scol1[512], scol2[512];
    __shared__ double srow1[40], srow2[40];
    __shared__ double rowPre1[41], rowPre2[41];
    __shared__ double colPre1[21], colPre2[21];
    __shared__ double colSuf1[21], colSuf2[21];
    __shared__ double spart1[16], spart2[16];
    __shared__ double sS1s, sS2s;
    __shared__ float PP1[41*41], PP2[41*41];
    extern __shared__ float sedge[];         // 40*512

    int b = blockIdx.x, tid = threadIdx.x;   // 512 threads

    if (b == NB) {
        // template sum / sumsq + zero the correlation accumulator
        float a1 = 0.f, a2 = 0.f, b1s = 0.f, b2s = 0.f;
#pragma unroll 4
        for (int y = 0; y < HH; y += 2) {
            float v0 = tp[y * WW + tid];
            float v1 = tp[(y + 1) * WW + tid];
            a1 += v0; b1s += v1;
            a2 = fmaf(v0, v0, a2); b2s = fmaf(v1, v1, b2s);
        }
        scol1[tid] = (double)a1 + (double)b1s;
        scol2[tid] = (double)a2 + (double)b2s;
        __syncthreads();
        for (int st = 256; st > 0; st >>= 1) {
            if (tid < st) { scol1[tid] += scol1[tid + st]; scol2[tid] += scol2[tid + st]; }
            __syncthreads();
        }
        if (tid == 0) { g_tstats[0] = scol1[0]; g_tstats[1] = scol2[0]; }
        for (int i = tid; i < NB * NS; i += 512) g_cc[i] = 0.f;
        return;
    }

    const float* im = fr + (size_t)b * NPIX;
    // full column sums (fp32 64-row slabs -> fp64)
    {
        double c1 = 0.0, c2d = 0.0;
        for (int s = 0; s < 8; ++s) {
            float a1 = 0.f, a2 = 0.f, b1s = 0.f, b2s = 0.f;
#pragma unroll 4
            for (int y = s * 64; y < s * 64 + 64; y += 2) {
                float v0 = im[y * WW + tid];
                float v1 = im[(y + 1) * WW + tid];
                a1 += v0; b1s += v1;
                a2 = fmaf(v0, v0, a2); b2s = fmaf(v1, v1, b2s);
            }
            c1  += (double)a1 + (double)b1s;
            c2d += (double)a2 + (double)b2s;
        }
        scol1[tid] = c1; scol2[tid] = c2d;
    }
    for (int idx = tid; idx < 40 * 512; idx += 512) {
        int r = idx >> 9, c = idx & 511;
        int y = (r < 20) ? r : (472 + r);
        sedge[idx] = im[y * WW + c];
    }
    __syncthreads();

    int wid = tid >> 5, lane = tid & 31;
    for (int r = wid; r < 40; r += 16) {
        double a = 0.0, c2 = 0.0;
        for (int c = lane; c < 512; c += 32) {
            double v = (double)sedge[r * 512 + c];
            a += v; c2 += v * v;
        }
#pragma unroll
        for (int s = 16; s > 0; s >>= 1) {
            a  += __shfl_down_sync(0xffffffffu, a, s);
            c2 += __shfl_down_sync(0xffffffffu, c2, s);
        }
        if (lane == 0) { srow1[r] = a; srow2[r] = c2; }
    }
    for (int idx = tid; idx < 41 * 41; idx += 512) { PP1[idx] = 0.f; PP2[idx] = 0.f; }
    __syncthreads();

    for (int idx = tid; idx < 1600; idx += 512) {
        int r = idx / 40, cc = idx - r * 40;
        int col = (cc < 20) ? cc : (472 + cc);
        float v = sedge[r * 512 + col];
        PP1[(r + 1) * 41 + cc + 1] = v;
        PP2[(r + 1) * 41 + cc + 1] = v * v;
    }
    {
        double a = scol1[tid], c2 = scol2[tid];
#pragma unroll
        for (int s = 16; s > 0; s >>= 1) {
            a  += __shfl_down_sync(0xffffffffu, a, s);
            c2 += __shfl_down_sync(0xffffffffu, c2, s);
        }
        if (lane == 0) { spart1[wid] = a; spart2[wid] = c2; }
    }
    __syncthreads();

    if (tid < 41) {
        float a = 0.f, c2 = 0.f;
        for (int c = 0; c < 41; ++c) {
            a  += PP1[tid * 41 + c]; PP1[tid * 41 + c] = a;
            c2 += PP2[tid * 41 + c]; PP2[tid * 41 + c] = c2;
        }
    }
    if (tid == 64)  { double a = 0; rowPre1[0] = 0; for (int r = 0; r < 40; ++r) { a += srow1[r]; rowPre1[r+1] = a; } }
    if (tid == 96)  { double a = 0; rowPre2[0] = 0; for (int r = 0; r < 40; ++r) { a += srow2[r]; rowPre2[r+1] = a; } }
    if (tid == 128) { double a = 0; colPre1[0] = 0; for (int c = 0; c < 20; ++c) { a += scol1[c]; colPre1[c+1] = a; } }
    if (tid == 160) { double a = 0; colPre2[0] = 0; for (int c = 0; c < 20; ++c) { a += scol2[c]; colPre2[c+1] = a; } }
    if (tid == 192) { double a = 0; colSuf1[20] = 0; for (int j = 19; j >= 0; --j) { a += scol1[492+j]; colSuf1[j] = a; } }
    if (tid == 224) { double a = 0; colSuf2[20] = 0; for (int j = 19; j >= 0; --j) { a += scol2[492+j]; colSuf2[j] = a; } }
    if (tid == 256) { double a = 0; for (int w = 0; w < 16; ++w) a += spart1[w]; sS1s = a; g_isum[b] = a; }
    if (tid == 288) { double a = 0; for (int w = 0; w < 16; ++w) a += spart2[w]; sS2s = a; }
    __syncthreads();

    if (tid < 41) {
        float a = 0.f, c2 = 0.f;
        for (int r = 0; r < 41; ++r) {
            a  += PP1[r * 41 + tid]; PP1[r * 41 + tid] = a;
            c2 += PP2[r * 41 + tid]; PP2[r * 41 + tid] = c2;
        }
    }
    __syncthreads();

#define RECT(PP, r0, r1, c0, c1) \
    (PP[(r1)*41+(c1)] - PP[(r0)*41+(c1)] - PP[(r1)*41+(c0)] + PP[(r0)*41+(c0)])
    if (tid < NS) {
        int p = tid / SH, j = tid - p * SH;
        double rsum1 = rowPre1[p] + (rowPre1[40] - rowPre1[p + 20]);
        double rsum2 = rowPre2[p] + (rowPre2[40] - rowPre2[p + 20]);
        double csum1 = colPre1[j] + colSuf1[j];
        double csum2 = colPre2[j] + colSuf2[j];
        float q1 = RECT(PP1, 0, p, 0, j) + RECT(PP1, 0, p, 20 + j, 40)
                 + RECT(PP1, p + 20, 40, 0, j) + RECT(PP1, p + 20, 40, 20 + j, 40);
        float q2 = RECT(PP2, 0, p, 0, j) + RECT(PP2, 0, p, 20 + j, 40)
                 + RECT(PP2, p + 20, 40, 0, j) + RECT(PP2, p + 20, 40, 20 + j, 40);
        double w1 = sS1s - rsum1 - csum1 + (double)q1;
        double w2 = sS2s - rsum2 - csum2 + (double)q2;
        double m1 = w1 / KAREA;
        double m2 = w2 / KAREA;
        double var = m2 - m1 * m1 / KAREA + EPS;
        float vf = (float)var;
        if (vf < 0.f) vf = 0.f;
        g_den[(size_t)b * NS + tid] = sqrtf(vf);
    }
#undef RECT
}

// ---------------- K2: the correlation (hot kernel; R4 compute) ----------------
template<bool LAST>
__device__ __forceinline__ void corr_iter(const float* __restrict__ trow,
                                          const float* __restrict__ irow,
                                          float win[32], float acc[SH], float4& cur) {
#pragma unroll
    for (int sg = 0; sg < 8; ++sg) {
        float4 nxt = *(const float4*)(irow + 4 * sg + 4);
        float4 nw;
        const bool refill = (!LAST) || (sg <= 4);
        if (refill) nw = *(const float4*)(trow + 4 * sg + 32);
#pragma unroll
        for (int j = 0; j < SH; ++j) acc[j] = fmaf(cur.x, win[(4*sg + 0 + 20 - j) & 31], acc[j]);
#pragma unroll
        for (int j = 0; j < SH; ++j) acc[j] = fmaf(cur.y, win[(4*sg + 1 + 20 - j) & 31], acc[j]);
#pragma unroll
        for (int j = 0; j < SH; ++j) acc[j] = fmaf(cur.z, win[(4*sg + 2 + 20 - j) & 31], acc[j]);
#pragma unroll
        for (int j = 0; j < SH; ++j) acc[j] = fmaf(cur.w, win[(4*sg + 3 + 20 - j) & 31], acc[j]);
        if (refill) {
            win[(4*sg + 0) & 31] = nw.x;
            win[(4*sg + 1) & 31] = nw.y;
            win[(4*sg + 2) & 31] = nw.z;
            win[(4*sg + 3) & 31] = nw.w;
        }
        cur = nxt;
    }
}

__global__ void __launch_bounds__(CORR_THREADS, 2)
k_corr(const float* __restrict__ fr, const float* __restrict__ tp) {
    int b = blockIdx.x;
    int band = blockIdx.y;
    int y0 = band * TB;
    extern __shared__ float sm[];
    float* sm_t = sm;                       // TROWS x TCOLS
    float* sm_i = sm + TROWS * TCOLS;       // TB x ISTR
    int tid = threadIdx.x;

    // template main body (cols 10..521) as float2; wrap edges scalar
    for (int idx = tid; idx < TROWS * 256; idx += CORR_THREADS) {
        int r = idx >> 8, c2 = idx & 255;
        int gy = (y0 - MS + r) & (HH - 1);
        float2 v = *(const float2*)(tp + gy * WW + 2 * c2);
        *(float2*)(sm_t + r * TCOLS + 10 + 2 * c2) = v;
    }
    for (int idx = tid; idx < TROWS * 20; idx += CORR_THREADS) {
        int r = idx / 20, e = idx - r * 20;
        int c = (e < 10) ? e : (e + 512);
        int gy = (y0 - MS + r) & (HH - 1);
        int gx = (c - 10) & (WW - 1);
        sm_t[r * TCOLS + c] = tp[gy * WW + gx];
    }
    // image band as float4
    const float* im = fr + (size_t)b * NPIX + (size_t)y0 * WW;
    for (int idx = tid; idx < TB * 128; idx += CORR_THREADS) {
        int r = idx >> 7, c4 = idx & 127;
        *(float4*)(sm_i + r * ISTR + 4 * c4) = *(const float4*)(im + r * WW + 4 * c4);
    }
    __syncthreads();

    int yl = tid & 15;
    int p  = tid >> 4;
    const float* trow = sm_t + (yl + 2 * MS - p) * TCOLS;
    const float* irow = sm_i + yl * ISTR;

    float acc[SH];
#pragma unroll
    for (int j = 0; j < SH; ++j) acc[j] = 0.f;

    float win[32];
#pragma unroll
    for (int m = 0; m < 8; ++m) {
        float4 t = *(const float4*)(trow + 4 * m);
        win[4*m + 0] = t.x; win[4*m + 1] = t.y; win[4*m + 2] = t.z; win[4*m + 3] = t.w;
    }
    float4 cur = *(const float4*)irow;

    const float* tr = trow;
    const float* ir = irow;
#pragma unroll 1
    for (int it = 0; it < 15; ++it) {
        corr_iter<false>(tr, ir, win, acc, cur);
        tr += 32; ir += 32;
    }
    corr_iter<true>(tr, ir, win, acc, cur);
    __syncthreads();

    float* sred = sm;                        // reuse: 441*16 floats
#pragma unroll
    for (int j = 0; j < SH; ++j) sred[(p * SH + j) * 16 + yl] = acc[j];
    __syncthreads();
    for (int s = tid; s < NS; s += CORR_THREADS) {
        float v = 0.f;
#pragma unroll
        for (int k = 0; k < 16; ++k) v += sred[s * 16 + k];
        atomicAdd(&g_cc[(size_t)b * NS + s], v);
    }
}

// ---------------- K3: ncc, argmax, subpixel shift ----------------
__global__ void k_peak() {
    int b = blockIdx.x, tid = threadIdx.x;
    __shared__ float sncc[NS];
    __shared__ float rv[512];
    __shared__ int   ri[512];
    double tsum = g_tstats[0], tsum2 = g_tstats[1];
    float stv  = sqrtf((float)(tsum2 - tsum * tsum / (double)NPIX + EPS));
    float cfix = (float)(g_isum[b] * tsum / (double)NPIX);
    if (tid < NS) {
        float ccv = fabsf(g_cc[(size_t)b * NS + tid] - cfix);
        float v = ccv / (stv * g_den[(size_t)b * NS + tid]);
        if (!(v == v)) v = 0.f;
        sncc[tid] = v;
    }
    __syncthreads();
    rv[tid] = (tid < NS) ? sncc[tid] : -1.f;
    ri[tid] = tid;
    __syncthreads();
    for (int st = 256; st > 0; st >>= 1) {
        if (tid < st) {
            float ov = rv[tid + st]; int oi = ri[tid + st];
            if (ov > rv[tid] || (ov == rv[tid] && oi < ri[tid])) { rv[tid] = ov; ri[tid] = oi; }
        }
        __syncthreads();
    }
    if (tid == 0) {
        int am = ri[0];
        int sx = am / SH, sy = am - sx * SH;
        float shx = -(float)(sx - MS);
        float shy = -(float)(sy - MS);
        int xm = sx - 1; if (xm < 0) xm += SH;
        int xp = sx + 1; if (xp > SH - 1) xp = SH - 1;
        int ym = sy - 1; if (ym < 0) ym += SH;
        int yp = sy + 1; if (yp > SH - 1) yp = SH - 1;
        float lxm = logf(sncc[xm * SH + sy]);
        float lxp = logf(sncc[xp * SH + sy]);
        float lym = logf(sncc[sx * SH + ym]);
        float lyp = logf(sncc[sx * SH + yp]);
        float lc4 = 4.f * logf(sncc[sx * SH + sy]);
        shx -= (lxm - lxp) / (2.f * lxm - lc4 + 2.f * lxp);
        shy -= (lym - lyp) / (2.f * lym - lc4 + 2.f * lyp);
        g_shift[b * 2 + 0] = shx;
        g_shift[b * 2 + 1] = shy;
    }
}

// ---------------- K4: bilinear warp + transposed store ----------------
__global__ void k_warp(const float* __restrict__ fr, float* __restrict__ out) {
    int b = blockIdx.z;
    int X0 = blockIdx.x * 32, Y0 = blockIdx.y * 32;
    float dy = g_shift[b * 2 + 0];
    float dx = g_shift[b * 2 + 1];
    __shared__ float sp[36 * 37];
    int ry = Y0 + (int)floorf(-dy) - 1;
    int rx = X0 + (int)floorf(-dx) - 1;
    const float* im = fr + (size_t)b * NPIX;
    for (int idx = threadIdx.x; idx < 36 * 36; idx += 256) {
        int r = idx / 36, c = idx - r * 36;
        int gy = ry + r, gx = rx + c;
        float v = (gy >= 0 && gy < HH && gx >= 0 && gx < WW) ? im[gy * WW + gx] : 0.f;
        sp[r * 37 + c] = v;
    }
    __syncthreads();
    int oy = threadIdx.x & 31;
    int oxb = threadIdx.x >> 5;
    for (int k = 0; k < 4; ++k) {
        int ox = oxb + 8 * k;
        int y = Y0 + oy, x = X0 + ox;
        float yq = (float)y - dy; float y0f = floorf(yq); float wy = yq - y0f;
        float xq = (float)x - dx; float x0f = floorf(xq); float wx = xq - x0f;
        int iy = (int)y0f - ry; int ix = (int)x0f - rx;
        iy = max(0, min(34, iy)); ix = max(0, min(34, ix));
        float v00 = sp[iy * 37 + ix];
        float v01 = sp[iy * 37 + ix + 1];
        float v10 = sp[(iy + 1) * 37 + ix];
        float v11 = sp[(iy + 1) * 37 + ix + 1];
        float val = v00 * (1.f - wy) * (1.f - wx) + v01 * (1.f - wy) * wx
                  + v10 * wy * (1.f - wx) + v11 * wy * wx;
        out[(size_t)b * NPIX + x * HH + y] = val;
    }
}

// ---------------- launch ----------------
extern "C" void kernel_launch(void* const* d_in, const int* in_sizes, int n_in,
                              void* d_out, int out_size) {
    const float* fr = (const float*)d_in[0];
    const float* tp = (const float*)d_in[1];
    if (n_in >= 2 && in_sizes[0] < in_sizes[1]) { const float* t = fr; fr = tp; tp = t; }
    float* out = (float*)d_out;

    cudaFuncSetAttribute(k_corr,  cudaFuncAttributeMaxDynamicSharedMemorySize, SMEM_CORR);
    cudaFuncSetAttribute(k_front, cudaFuncAttributeMaxDynamicSharedMemorySize, SMEM_FRONT);

    k_front<<<NB + 1, 512, SMEM_FRONT>>>(fr, tp);
    k_corr<<<dim3(NB, NBAND), CORR_THREADS, SMEM_CORR>>>(fr, tp);
    k_peak<<<NB, 512>>>();
    k_warp<<<dim3(16, 16, NB), 256>>>(fr, out);
}

// round 10
// speedup vs baseline: 1.1887x; 1.0463x over previous
#include <cuda_runtime.h>
#include <math.h>

#define HH 512
#define WW 512
#define NB 32
#define MS 10
#define SH 21            // 2*MS+1
#define NS 441           // SH*SH
#define NPIX (HH*WW)     // 262144
#define KAREA (492.0*492.0)
#define EPS 1e-8

#define TB 16                    // rows per correlation band
#define NBAND (HH/TB)            // 32
#define TROWS (TB + 20)          // 36
#define TCOLS (WW + 20)          // 532
#define ISTR 516
#define CORR_THREADS 336         // 21 p-values x 16 rows
#define SMEM_CORR ((TROWS*TCOLS + TB*ISTR) * 4)   // 109632
#define SMEM_STATS (40*512*4)

// ---------------- scratch ----------------
__device__ double g_tstats[2];
__device__ double g_isum[NB];
__device__ double g_colF1[NB*WW];
__device__ double g_colF2[NB*WW];
__device__ float  g_den[NB*NS];            // sqrt(window var)
__device__ float  g_cc[NB*NS];             // accumulated correlations
__device__ float  g_shift[NB*2];

// ---------------- K0: zero atomic targets ----------------
__global__ void k_zero() {
    int i = blockIdx.x * blockDim.x + threadIdx.x;
    if (i < NB * WW) { g_colF1[i] = 0.0; g_colF2[i] = 0.0; }
    if (i < NB * NS) g_cc[i] = 0.f;
    if (i < 2) g_tstats[i] = 0.0;
}

// ---------------- K1: column partial sums + template stats ----------------
__global__ void k_colpart(const float* __restrict__ fr, const float* __restrict__ tp) {
    int b = blockIdx.x;
    int slab = blockIdx.y;
    int x = threadIdx.x;
    const float* src = (b < NB) ? (fr + (size_t)b * NPIX) : tp;
    int y0 = slab * 64;
    float s1a = 0.f, s1b = 0.f, s2a = 0.f, s2b = 0.f;
#pragma unroll 4
    for (int y = y0; y < y0 + 64; y += 2) {
        float v0 = src[y * WW + x];
        float v1 = src[(y + 1) * WW + x];
        s1a += v0; s1b += v1;
        s2a = fmaf(v0, v0, s2a); s2b = fmaf(v1, v1, s2b);
    }
    double d1 = (double)s1a + (double)s1b;
    double d2 = (double)s2a + (double)s2b;
    if (b < NB) {
        atomicAdd(&g_colF1[b * WW + x], d1);
        atomicAdd(&g_colF2[b * WW + x], d2);
    } else {
        __shared__ double r1[512], r2[512];
        r1[x] = d1; r2[x] = d2;
        __syncthreads();
        for (int st = 256; st > 0; st >>= 1) {
            if (x < st) { r1[x] += r1[x + st]; r2[x] += r2[x + st]; }
            __syncthreads();
        }
        if (x == 0) {
            atomicAdd(&g_tstats[0], r1[0]);
            atomicAdd(&g_tstats[1], r2[0]);
        }
    }
}

// ---------------- K2: all 441 window denominators per frame ----------------
__global__ void __launch_bounds__(512) k_stats(const float* __restrict__ fr) {
    __shared__ double scol1[512], scol2[512];
    __shared__ double srow1[40], srow2[40];
    __shared__ double rowPre1[41], rowPre2[41];
    __shared__ double colPre1[21], colPre2[21];
    __shared__ double colSuf1[21], colSuf2[21];
    __shared__ double spart1[16], spart2[16];
    __shared__ double sS1s, sS2s;
    __shared__ float PP1[41*41], PP2[41*41];
    extern __shared__ float sedge[];         // 40*512

    int b = blockIdx.x, tid = threadIdx.x;   // 512 threads
    scol1[tid] = g_colF1[b * WW + tid];
    scol2[tid] = g_colF2[b * WW + tid];
    const float* im = fr + (size_t)b * NPIX;
    for (int idx = tid; idx < 40 * 512; idx += 512) {
        int r = idx >> 9, c = idx & 511;
        int y = (r < 20) ? r : (472 + r);
        sedge[idx] = im[y * WW + c];
    }
    __syncthreads();

    int wid = tid >> 5, lane = tid & 31;
    for (int r = wid; r < 40; r += 16) {
        double a = 0.0, c2 = 0.0;
        for (int c = lane; c < 512; c += 32) {
            double v = (double)sedge[r * 512 + c];
            a += v; c2 += v * v;
        }
#pragma unroll
        for (int s = 16; s > 0; s >>= 1) {
            a  += __shfl_down_sync(0xffffffffu, a, s);
            c2 += __shfl_down_sync(0xffffffffu, c2, s);
        }
        if (lane == 0) { srow1[r] = a; srow2[r] = c2; }
    }
    for (int idx = tid; idx < 41 * 41; idx += 512) { PP1[idx] = 0.f; PP2[idx] = 0.f; }
    __syncthreads();

    for (int idx = tid; idx < 1600; idx += 512) {
        int r = idx / 40, cc = idx - r * 40;
        int col = (cc < 20) ? cc : (472 + cc);
        float v = sedge[r * 512 + col];
        PP1[(r + 1) * 41 + cc + 1] = v;
        PP2[(r + 1) * 41 + cc + 1] = v * v;
    }
    {
        double a = scol1[tid], c2 = scol2[tid];
#pragma unroll
        for (int s = 16; s > 0; s >>= 1) {
            a  += __shfl_down_sync(0xffffffffu, a, s);
            c2 += __shfl_down_sync(0xffffffffu, c2, s);
        }
        if (lane == 0) { spart1[wid] = a; spart2[wid] = c2; }
    }
    __syncthreads();

    if (tid < 41) {
        float a = 0.f, c2 = 0.f;
        for (int c = 0; c < 41; ++c) {
            a  += PP1[tid * 41 + c]; PP1[tid * 41 + c] = a;
            c2 += PP2[tid * 41 + c]; PP2[tid * 41 + c] = c2;
        }
    }
    if (tid == 64)  { double a = 0; rowPre1[0] = 0; for (int r = 0; r < 40; ++r) { a += srow1[r]; rowPre1[r+1] = a; } }
    if (tid == 96)  { double a = 0; rowPre2[0] = 0; for (int r = 0; r < 40; ++r) { a += srow2[r]; rowPre2[r+1] = a; } }
    if (tid == 128) { double a = 0; colPre1[0] = 0; for (int c = 0; c < 20; ++c) { a += scol1[c]; colPre1[c+1] = a; } }
    if (tid == 160) { double a = 0; colPre2[0] = 0; for (int c = 0; c < 20; ++c) { a += scol2[c]; colPre2[c+1] = a; } }
    if (tid == 192) { double a = 0; colSuf1[20] = 0; for (int j = 19; j >= 0; --j) { a += scol1[492+j]; colSuf1[j] = a; } }
    if (tid == 224) { double a = 0; colSuf2[20] = 0; for (int j = 19; j >= 0; --j) { a += scol2[492+j]; colSuf2[j] = a; } }
    if (tid == 256) { double a = 0; for (int w = 0; w < 16; ++w) a += spart1[w]; sS1s = a; g_isum[b] = a; }
    if (tid == 288) { double a = 0; for (int w = 0; w < 16; ++w) a += spart2[w]; sS2s = a; }
    __syncthreads();

    if (tid < 41) {
        float a = 0.f, c2 = 0.f;
        for (int r = 0; r < 41; ++r) {
            a  += PP1[r * 41 + tid]; PP1[r * 41 + tid] = a;
            c2 += PP2[r * 41 + tid]; PP2[r * 41 + tid] = c2;
        }
    }
    __syncthreads();

#define RECT(PP, r0, r1, c0, c1) \
    (PP[(r1)*41+(c1)] - PP[(r0)*41+(c1)] - PP[(r1)*41+(c0)] + PP[(r0)*41+(c0)])
    if (tid < NS) {
        int p = tid / SH, j = tid - p * SH;
        double rsum1 = rowPre1[p] + (rowPre1[40] - rowPre1[p + 20]);
        double rsum2 = rowPre2[p] + (rowPre2[40] - rowPre2[p + 20]);
        double csum1 = colPre1[j] + colSuf1[j];
        double csum2 = colPre2[j] + colSuf2[j];
        float q1 = RECT(PP1, 0, p, 0, j) + RECT(PP1, 0, p, 20 + j, 40)
                 + RECT(PP1, p + 20, 40, 0, j) + RECT(PP1, p + 20, 40, 20 + j, 40);
        float q2 = RECT(PP2, 0, p, 0, j) + RECT(PP2, 0, p, 20 + j, 40)
                 + RECT(PP2, p + 20, 40, 0, j) + RECT(PP2, p + 20, 40, 20 + j, 40);
        double w1 = sS1s - rsum1 - csum1 + (double)q1;
        double w2 = sS2s - rsum2 - csum2 + (double)q2;
        double m1 = w1 / KAREA;
        double m2 = w2 / KAREA;
        double var = m2 - m1 * m1 / KAREA + EPS;
        float vf = (float)var;
        if (vf < 0.f) vf = 0.f;
        g_den[(size_t)b * NS + tid] = sqrtf(vf);
    }
#undef RECT
}

// ---------------- K3: the correlation (hot kernel; R9 compute, unchanged) ----------------
template<bool LAST>
__device__ __forceinline__ void corr_iter(const float* __restrict__ trow,
                                          const float* __restrict__ irow,
                                          float win[32], float acc[SH], float4& cur) {
#pragma unroll
    for (int sg = 0; sg < 8; ++sg) {
        float4 nxt = *(const float4*)(irow + 4 * sg + 4);
        float4 nw;
        const bool refill = (!LAST) || (sg <= 4);
        if (refill) nw = *(const float4*)(trow + 4 * sg + 32);
#pragma unroll
        for (int j = 0; j < SH; ++j) acc[j] = fmaf(cur.x, win[(4*sg + 0 + 20 - j) & 31], acc[j]);
#pragma unroll
        for (int j = 0; j < SH; ++j) acc[j] = fmaf(cur.y, win[(4*sg + 1 + 20 - j) & 31], acc[j]);
#pragma unroll
        for (int j = 0; j < SH; ++j) acc[j] = fmaf(cur.z, win[(4*sg + 2 + 20 - j) & 31], acc[j]);
#pragma unroll
        for (int j = 0; j < SH; ++j) acc[j] = fmaf(cur.w, win[(4*sg + 3 + 20 - j) & 31], acc[j]);
        if (refill) {
            win[(4*sg + 0) & 31] = nw.x;
            win[(4*sg + 1) & 31] = nw.y;
            win[(4*sg + 2) & 31] = nw.z;
            win[(4*sg + 3) & 31] = nw.w;
        }
        cur = nxt;
    }
}

__global__ void __launch_bounds__(CORR_THREADS, 2)
k_corr(const float* __restrict__ fr, const float* __restrict__ tp) {
    int b = blockIdx.x;
    int band = blockIdx.y;
    int y0 = band * TB;
    extern __shared__ float sm[];
    float* sm_t = sm;                       // TROWS x TCOLS
    float* sm_i = sm + TROWS * TCOLS;       // TB x ISTR
    int tid = threadIdx.x;

    for (int idx = tid; idx < TROWS * 256; idx += CORR_THREADS) {
        int r = idx >> 8, c2 = idx & 255;
        int gy = (y0 - MS + r) & (HH - 1);
        float2 v = *(const float2*)(tp + gy * WW + 2 * c2);
        *(float2*)(sm_t + r * TCOLS + 10 + 2 * c2) = v;
    }
    for (int idx = tid; idx < TROWS * 20; idx += CORR_THREADS) {
        int r = idx / 20, e = idx - r * 20;
        int c = (e < 10) ? e : (e + 512);
        int gy = (y0 - MS + r) & (HH - 1);
        int gx = (c - 10) & (WW - 1);
        sm_t[r * TCOLS + c] = tp[gy * WW + gx];
    }
    const float* im = fr + (size_t)b * NPIX + (size_t)y0 * WW;
    for (int idx = tid; idx < TB * 128; idx += CORR_THREADS) {
        int r = idx >> 7, c4 = idx & 127;
        *(float4*)(sm_i + r * ISTR + 4 * c4) = *(const float4*)(im + r * WW + 4 * c4);
    }
    __syncthreads();

    int yl = tid & 15;
    int p  = tid >> 4;
    const float* trow = sm_t + (yl + 2 * MS - p) * TCOLS;
    const float* irow = sm_i + yl * ISTR;

    float acc[SH];
#pragma unroll
    for (int j = 0; j < SH; ++j) acc[j] = 0.f;

    float win[32];
#pragma unroll
    for (int m = 0; m < 8; ++m) {
        float4 t = *(const float4*)(trow + 4 * m);
        win[4*m + 0] = t.x; win[4*m + 1] = t.y; win[4*m + 2] = t.z; win[4*m + 3] = t.w;
    }
    float4 cur = *(const float4*)irow;

    const float* tr = trow;
    const float* ir = irow;
#pragma unroll 1
    for (int it = 0; it < 15; ++it) {
        corr_iter<false>(tr, ir, win, acc, cur);
        tr += 32; ir += 32;
    }
    corr_iter<true>(tr, ir, win, acc, cur);
    __syncthreads();

    float* sred = sm;                        // reuse: 441*16 floats
#pragma unroll
    for (int j = 0; j < SH; ++j) sred[(p * SH + j) * 16 + yl] = acc[j];
    __syncthreads();
    for (int s = tid; s < NS; s += CORR_THREADS) {
        float v = 0.f;
#pragma unroll
        for (int k = 0; k < 16; ++k) v += sred[s * 16 + k];
        atomicAdd(&g_cc[(size_t)b * NS + s], v);
    }
}

// ---------------- K4: ncc, argmax, subpixel shift ----------------
__global__ void k_peak() {
    int b = blockIdx.x, tid = threadIdx.x;
    __shared__ float sncc[NS];
    __shared__ float rv[512];
    __shared__ int   ri[512];
    double tsum = g_tstats[0], tsum2 = g_tstats[1];
    float stv  = sqrtf((float)(tsum2 - tsum * tsum / (double)NPIX + EPS));
    float cfix = (float)(g_isum[b] * tsum / (double)NPIX);
    if (tid < NS) {
        float ccv = fabsf(g_cc[(size_t)b * NS + tid] - cfix);
        float v = ccv / (stv * g_den[(size_t)b * NS + tid]);
        if (!(v == v)) v = 0.f;
        sncc[tid] = v;
    }
    __syncthreads();
    rv[tid] = (tid < NS) ? sncc[tid] : -1.f;
    ri[tid] = tid;
    __syncthreads();
    for (int st = 256; st > 0; st >>= 1) {
        if (tid < st) {
            float ov = rv[tid + st]; int oi = ri[tid + st];
            if (ov > rv[tid] || (ov == rv[tid] && oi < ri[tid])) { rv[tid] = ov; ri[tid] = oi; }
        }
        __syncthreads();
    }
    if (tid == 0) {
        int am = ri[0];
        int sx = am / SH, sy = am - sx * SH;
        float shx = -(float)(sx - MS);
        float shy = -(float)(sy - MS);
        int xm = sx - 1; if (xm < 0) xm += SH;
        int xp = sx + 1; if (xp > SH - 1) xp = SH - 1;
        int ym = sy - 1; if (ym < 0) ym += SH;
        int yp = sy + 1; if (yp > SH - 1) yp = SH - 1;
        float lxm = logf(sncc[xm * SH + sy]);
        float lxp = logf(sncc[xp * SH + sy]);
        float lym = logf(sncc[sx * SH + ym]);
        float lyp = logf(sncc[sx * SH + yp]);
        float lc4 = 4.f * logf(sncc[sx * SH + sy]);
        shx -= (lxm - lxp) / (2.f * lxm - lc4 + 2.f * lxp);
        shy -= (lym - lyp) / (2.f * lym - lc4 + 2.f * lyp);
        g_shift[b * 2 + 0] = shx;
        g_shift[b * 2 + 1] = shy;
    }
}

// ---------------- K5: bilinear warp (constant weights) + transposed store ----------------
__global__ void __launch_bounds__(256) k_warp(const float* __restrict__ fr,
                                              float* __restrict__ out) {
    int b = blockIdx.z;
    int X0 = blockIdx.x * 32, Y0 = blockIdx.y * 32;
    float dy = g_shift[b * 2 + 0];
    float dx = g_shift[b * 2 + 1];
    // y - dy has constant fractional part: Ay = floor(-dy), wy = frac(-dy)
    float fy = floorf(-dy), fx = floorf(-dx);
    int Ay = (int)fy, Ax = (int)fx;
    float wy = -dy - fy, wx = -dx - fx;
    float c00 = (1.f - wy) * (1.f - wx);
    float c01 = (1.f - wy) * wx;
    float c10 = wy * (1.f - wx);
    float c11 = wy * wx;

    __shared__ float sp[33 * 37];
    const float* im = fr + (size_t)b * NPIX;
    for (int idx = threadIdx.x; idx < 33 * 33; idx += 256) {
        int r = idx / 33, c = idx - r * 33;
        int gy = Y0 + Ay + r, gx = X0 + Ax + c;
        float v = (gy >= 0 && gy < HH && gx >= 0 && gx < WW) ? im[gy * WW + gx] : 0.f;
        sp[r * 37 + c] = v;
    }
    __syncthreads();

    int tx = threadIdx.x >> 3;            // 0..31 : x within tile
    int qy = (threadIdx.x & 7) << 2;      // 0,4,..,28 : y quad base
    float cA[5], cB[5];
#pragma unroll
    for (int i = 0; i < 5; ++i) {
        cA[i] = sp[(qy + i) * 37 + tx];
        cB[i] = sp[(qy + i) * 37 + tx + 1];
    }
    float4 o;
    o.x = fmaf(c00, cA[0], fmaf(c01, cB[0], fmaf(c10, cA[1], c11 * cB[1])));
    o.y = fmaf(c00, cA[1], fmaf(c01, cB[1], fmaf(c10, cA[2], c11 * cB[2])));
    o.z = fmaf(c00, cA[2], fmaf(c01, cB[2], fmaf(c10, cA[3], c11 * cB[3])));
    o.w = fmaf(c00, cA[3], fmaf(c01, cB[3], fmaf(c10, cA[4], c11 * cB[4])));
    *(float4*)(out + (size_t)b * NPIX + (size_t)(X0 + tx) * HH + Y0 + qy) = o;
}

// ---------------- launch ----------------
extern "C" void kernel_launch(void* const* d_in, const int* in_sizes, int n_in,
                              void* d_out, int out_size) {
    const float* fr = (const float*)d_in[0];
    const float* tp = (const float*)d_in[1];
    if (n_in >= 2 && in_sizes[0] < in_sizes[1]) { const float* t = fr; fr = tp; tp = t; }
    float* out = (float*)d_out;

    cudaFuncSetAttribute(k_corr,  cudaFuncAttributeMaxDynamicSharedMemorySize, SMEM_CORR);
    cudaFuncSetAttribute(k_stats, cudaFuncAttributeMaxDynamicSharedMemorySize, SMEM_STATS);

    k_zero<<<64, 512>>>();
    k_colpart<<<dim3(NB + 1, 8), 512>>>(fr, tp);
    k_stats<<<NB, 512, SMEM_STATS>>>(fr);
    k_corr<<<dim3(NB, NBAND), CORR_THREADS, SMEM_CORR>>>(fr, tp);
    k_peak<<<NB, 512>>>();
    k_warp<<<dim3(16, 16, NB), 256>>>(fr, out);
}

// round 11
// speedup vs baseline: 1.2058x; 1.0144x over previous
#include <cuda_runtime.h>
#include <math.h>

#define HH 512
#define WW 512
#define NB 32
#define MS 10
#define SH 21            // 2*MS+1
#define NS 441           // SH*SH
#define NPIX (HH*WW)     // 262144
#define KAREA (492.0*492.0)
#define EPS 1e-8

#define TBAND 14                 // image rows per band
#define NBAND 37                 // 37*14 = 518 >= 512 (last band 8 rows)
#define TROWS 34                 // TBAND + 20
#define TCOLS 532
#define ISTR 516
#define CTH 294                  // 21 p-values x 14 rows
#define SMEM_CORR ((TROWS*TCOLS + TBAND*ISTR) * 4)   // 101248
#define SMEM_STATS (40*512*4)

// ---------------- scratch ----------------
__device__ double g_tstats[2];
__device__ double g_isum[NB];
__device__ double g_colF1[NB*WW];
__device__ double g_colF2[NB*WW];
__device__ float  g_den[NB*NS];            // sqrt(window var)
__device__ float  g_cc[NB*NS];             // accumulated correlations
__device__ float  g_shift[NB*2];

// ---------------- K0: zero atomic targets ----------------
__global__ void k_zero() {
    int i = blockIdx.x * blockDim.x + threadIdx.x;
    if (i < NB * WW) { g_colF1[i] = 0.0; g_colF2[i] = 0.0; }
    if (i < NB * NS) g_cc[i] = 0.f;
    if (i < 2) g_tstats[i] = 0.0;
}

// ---------------- K1: column partial sums + template stats ----------------
__global__ void k_colpart(const float* __restrict__ fr, const float* __restrict__ tp) {
    int b = blockIdx.x;
    int slab = blockIdx.y;
    int x = threadIdx.x;
    const float* src = (b < NB) ? (fr + (size_t)b * NPIX) : tp;
    int y0 = slab * 64;
    float s1a = 0.f, s1b = 0.f, s2a = 0.f, s2b = 0.f;
#pragma unroll 4
    for (int y = y0; y < y0 + 64; y += 2) {
        float v0 = src[y * WW + x];
        float v1 = src[(y + 1) * WW + x];
        s1a += v0; s1b += v1;
        s2a = fmaf(v0, v0, s2a); s2b = fmaf(v1, v1, s2b);
    }
    double d1 = (double)s1a + (double)s1b;
    double d2 = (double)s2a + (double)s2b;
    if (b < NB) {
        atomicAdd(&g_colF1[b * WW + x], d1);
        atomicAdd(&g_colF2[b * WW + x], d2);
    } else {
        __shared__ double r1[512], r2[512];
        r1[x] = d1; r2[x] = d2;
        __syncthreads();
        for (int st = 256; st > 0; st >>= 1) {
            if (x < st) { r1[x] += r1[x + st]; r2[x] += r2[x + st]; }
            __syncthreads();
        }
        if (x == 0) {
            atomicAdd(&g_tstats[0], r1[0]);
            atomicAdd(&g_tstats[1], r2[0]);
        }
    }
}

// ---------------- K2: all 441 window denominators per frame ----------------
__global__ void __launch_bounds__(512) k_stats(const float* __restrict__ fr) {
    __shared__ double scol1[512], scol2[512];
    __shared__ double srow1[40], srow2[40];
    __shared__ double rowPre1[41], rowPre2[41];
    __shared__ double colPre1[21], colPre2[21];
    __shared__ double colSuf1[21], colSuf2[21];
    __shared__ double spart1[16], spart2[16];
    __shared__ double sS1s, sS2s;
    __shared__ float PP1[41*41], PP2[41*41];
    extern __shared__ float sedge[];         // 40*512

    int b = blockIdx.x, tid = threadIdx.x;   // 512 threads
    scol1[tid] = g_colF1[b * WW + tid];
    scol2[tid] = g_colF2[b * WW + tid];
    const float* im = fr + (size_t)b * NPIX;
    for (int idx = tid; idx < 40 * 512; idx += 512) {
        int r = idx >> 9, c = idx & 511;
        int y = (r < 20) ? r : (472 + r);
        sedge[idx] = im[y * WW + c];
    }
    __syncthreads();

    int wid = tid >> 5, lane = tid & 31;
    for (int r = wid; r < 40; r += 16) {
        double a = 0.0, c2 = 0.0;
        for (int c = lane; c < 512; c += 32) {
            double v = (double)sedge[r * 512 + c];
            a += v; c2 += v * v;
        }
#pragma unroll
        for (int s = 16; s > 0; s >>= 1) {
            a  += __shfl_down_sync(0xffffffffu, a, s);
            c2 += __shfl_down_sync(0xffffffffu, c2, s);
        }
        if (lane == 0) { srow1[r] = a; srow2[r] = c2; }
    }
    for (int idx = tid; idx < 41 * 41; idx += 512) { PP1[idx] = 0.f; PP2[idx] = 0.f; }
    __syncthreads();

    for (int idx = tid; idx < 1600; idx += 512) {
        int r = idx / 40, cc = idx - r * 40;
        int col = (cc < 20) ? cc : (472 + cc);
        float v = sedge[r * 512 + col];
        PP1[(r + 1) * 41 + cc + 1] = v;
        PP2[(r + 1) * 41 + cc + 1] = v * v;
    }
    {
        double a = scol1[tid], c2 = scol2[tid];
#pragma unroll
        for (int s = 16; s > 0; s >>= 1) {
            a  += __shfl_down_sync(0xffffffffu, a, s);
            c2 += __shfl_down_sync(0xffffffffu, c2, s);
        }
        if (lane == 0) { spart1[wid] = a; spart2[wid] = c2; }
    }
    __syncthreads();

    if (tid < 41) {
        float a = 0.f, c2 = 0.f;
        for (int c = 0; c < 41; ++c) {
            a  += PP1[tid * 41 + c]; PP1[tid * 41 + c] = a;
            c2 += PP2[tid * 41 + c]; PP2[tid * 41 + c] = c2;
        }
    }
    if (tid == 64)  { double a = 0; rowPre1[0] = 0; for (int r = 0; r < 40; ++r) { a += srow1[r]; rowPre1[r+1] = a; } }
    if (tid == 96)  { double a = 0; rowPre2[0] = 0; for (int r = 0; r < 40; ++r) { a += srow2[r]; rowPre2[r+1] = a; } }
    if (tid == 128) { double a = 0; colPre1[0] = 0; for (int c = 0; c < 20; ++c) { a += scol1[c]; colPre1[c+1] = a; } }
    if (tid == 160) { double a = 0; colPre2[0] = 0; for (int c = 0; c < 20; ++c) { a += scol2[c]; colPre2[c+1] = a; } }
    if (tid == 192) { double a = 0; colSuf1[20] = 0; for (int j = 19; j >= 0; --j) { a += scol1[492+j]; colSuf1[j] = a; } }
    if (tid == 224) { double a = 0; colSuf2[20] = 0; for (int j = 19; j >= 0; --j) { a += scol2[492+j]; colSuf2[j] = a; } }
    if (tid == 256) { double a = 0; for (int w = 0; w < 16; ++w) a += spart1[w]; sS1s = a; g_isum[b] = a; }
    if (tid == 288) { double a = 0; for (int w = 0; w < 16; ++w) a += spart2[w]; sS2s = a; }
    __syncthreads();

    if (tid < 41) {
        float a = 0.f, c2 = 0.f;
        for (int r = 0; r < 41; ++r) {
            a  += PP1[r * 41 + tid]; PP1[r * 41 + tid] = a;
            c2 += PP2[r * 41 + tid]; PP2[r * 41 + tid] = c2;
        }
    }
    __syncthreads();

#define RECT(PP, r0, r1, c0, c1) \
    (PP[(r1)*41+(c1)] - PP[(r0)*41+(c1)] - PP[(r1)*41+(c0)] + PP[(r0)*41+(c0)])
    if (tid < NS) {
        int p = tid / SH, j = tid - p * SH;
        double rsum1 = rowPre1[p] + (rowPre1[40] - rowPre1[p + 20]);
        double rsum2 = rowPre2[p] + (rowPre2[40] - rowPre2[p + 20]);
        double csum1 = colPre1[j] + colSuf1[j];
        double csum2 = colPre2[j] + colSuf2[j];
        float q1 = RECT(PP1, 0, p, 0, j) + RECT(PP1, 0, p, 20 + j, 40)
                 + RECT(PP1, p + 20, 40, 0, j) + RECT(PP1, p + 20, 40, 20 + j, 40);
        float q2 = RECT(PP2, 0, p, 0, j) + RECT(PP2, 0, p, 20 + j, 40)
                 + RECT(PP2, p + 20, 40, 0, j) + RECT(PP2, p + 20, 40, 20 + j, 40);
        double w1 = sS1s - rsum1 - csum1 + (double)q1;
        double w2 = sS2s - rsum2 - csum2 + (double)q2;
        double m1 = w1 / KAREA;
        double m2 = w2 / KAREA;
        double var = m2 - m1 * m1 / KAREA + EPS;
        float vf = (float)var;
        if (vf < 0.f) vf = 0.f;
        g_den[(size_t)b * NS + tid] = sqrtf(vf);
    }
#undef RECT
}

// ---------------- K3: the correlation (hot kernel) ----------------
template<int SLOT>
__device__ __forceinline__ float wslot(const float4* w) {
    return ((SLOT & 3) == 0) ? w[(SLOT >> 2) & 7].x
         : ((SLOT & 3) == 1) ? w[(SLOT >> 2) & 7].y
         : ((SLOT & 3) == 2) ? w[(SLOT >> 2) & 7].z
                             : w[(SLOT >> 2) & 7].w;
}

template<int X, int J> struct FmaJ {
    static __device__ __forceinline__ void run(float v, const float4* w, float* acc) {
        acc[J] = fmaf(v, wslot<(X + 20 - J) & 31>(w), acc[J]);
        FmaJ<X, J + 1>::run(v, w, acc);
    }
};
template<int X> struct FmaJ<X, SH> {
    static __device__ __forceinline__ void run(float, const float4*, float*) {}
};

template<int SG, bool LAST> struct Step {
    static __device__ __forceinline__ void run(const float* __restrict__ tr,
                                               const float* __restrict__ ir,
                                               float4* w, float4* iv, float* acc) {
        iv[(SG + 1) & 1] = *(const float4*)(ir + 4 * SG + 4);   // prefetch next 4 px
        FmaJ<4 * SG + 0, 0>::run(iv[SG & 1].x, w, acc);
        FmaJ<4 * SG + 1, 0>::run(iv[SG & 1].y, w, acc);
        FmaJ<4 * SG + 2, 0>::run(iv[SG & 1].z, w, acc);
        FmaJ<4 * SG + 3, 0>::run(iv[SG & 1].w, w, acc);
        if (!LAST || SG <= 4)
            w[SG] = *(const float4*)(tr + 4 * SG + 32);         // refill dead quad
        Step<SG + 1, LAST>::run(tr, ir, w, iv, acc);
    }
};
template<bool LAST> struct Step<8, LAST> {
    static __device__ __forceinline__ void run(const float*, const float*,
                                               float4*, float4*, float*) {}
};

__global__ void __launch_bounds__(CTH, 2)
k_corr(const float* __restrict__ fr, const float* __restrict__ tp) {
    int band = blockIdx.x;                  // 0..36
    int fg   = blockIdx.y;                  // 0..7 (4 frames each)
    int y0 = band * TBAND;
    extern __shared__ float sm[];
    float* sm_t = sm;                       // TROWS x TCOLS
    float* sm_i = sm + TROWS * TCOLS;       // TBAND x ISTR
    int tid = threadIdx.x;

    // template tile once per block (shared by 4 frames); wrapped rows/cols
    for (int idx = tid; idx < TROWS * 256; idx += CTH) {
        int r = idx >> 8, c2 = idx & 255;
        int gy = (y0 - MS + r) & (HH - 1);
        float2 v = *(const float2*)(tp + gy * WW + 2 * c2);
        *(float2*)(sm_t + r * TCOLS + 10 + 2 * c2) = v;
    }
    for (int idx = tid; idx < TROWS * 20; idx += CTH) {
        int r = idx / 20, e = idx - r * 20;
        int c = (e < 10) ? e : (e + 512);
        int gy = (y0 - MS + r) & (HH - 1);
        int gx = (c - 10) & (WW - 1);
        sm_t[r * TCOLS + c] = tp[gy * WW + gx];
    }

    int yl = tid % TBAND;                   // image row in band
    int p  = tid / TBAND;                   // shift-row index 0..20
    const float* trow0 = sm_t + (yl + 2 * MS - p) * TCOLS;
    const float* irow0 = sm_i + yl * ISTR;

    for (int f = 0; f < 4; ++f) {
        int b = fg * 4 + f;
        const float* im = fr + (size_t)b * NPIX + (size_t)y0 * WW;
        __syncthreads();                    // sred of prev frame fully consumed
        for (int idx = tid; idx < TBAND * 128; idx += CTH) {
            int r = idx >> 7, c4 = idx & 127;
            float4 v;
            if (y0 + r < HH) v = *(const float4*)(im + r * WW + 4 * c4);
            else             v = make_float4(0.f, 0.f, 0.f, 0.f);
            *(float4*)(sm_i + r * ISTR + 4 * c4) = v;
        }
        __syncthreads();

        float acc[SH];
#pragma unroll
        for (int j = 0; j < SH; ++j) acc[j] = 0.f;
        float4 w[8];
#pragma unroll
        for (int m = 0; m < 8; ++m) w[m] = *(const float4*)(trow0 + 4 * m);
        float4 iv[2];
        iv[0] = *(const float4*)irow0;

        const float* tr = trow0;
        const float* ir = irow0;
#pragma unroll 1
        for (int it = 0; it < 15; ++it) {
            Step<0, false>::run(tr, ir, w, iv, acc);
            tr += 32; ir += 32;
        }
        Step<0, true>::run(tr, ir, w, iv, acc);

        __syncthreads();                    // all reads of sm_i done
        float* sred = sm_i;                 // reuse image buffer: 441*14 floats
#pragma unroll
        for (int j = 0; j < SH; ++j) sred[(p * SH + j) * TBAND + yl] = acc[j];
        __syncthreads();
        for (int s = tid; s < NS; s += CTH) {
            float v = 0.f;
#pragma unroll
            for (int k = 0; k < TBAND; ++k) v += sred[s * TBAND + k];
            atomicAdd(&g_cc[(size_t)b * NS + s], v);
        }
    }
}

// ---------------- K4: ncc, argmax, subpixel shift ----------------
__global__ void k_peak() {
    int b = blockIdx.x, tid = threadIdx.x;
    __shared__ float sncc[NS];
    __shared__ float rv[512];
    __shared__ int   ri[512];
    double tsum = g_tstats[0], tsum2 = g_tstats[1];
    float stv  = sqrtf((float)(tsum2 - tsum * tsum / (double)NPIX + EPS));
    float cfix = (float)(g_isum[b] * tsum / (double)NPIX);
    if (tid < NS) {
        float ccv = fabsf(g_cc[(size_t)b * NS + tid] - cfix);
        float v = ccv / (stv * g_den[(size_t)b * NS + tid]);
        if (!(v == v)) v = 0.f;
        sncc[tid] = v;
    }
    __syncthreads();
    rv[tid] = (tid < NS) ? sncc[tid] : -1.f;
    ri[tid] = tid;
    __syncthreads();
    for (int st = 256; st > 0; st >>= 1) {
        if (tid < st) {
            float ov = rv[tid + st]; int oi = ri[tid + st];
            if (ov > rv[tid] || (ov == rv[tid] && oi < ri[tid])) { rv[tid] = ov; ri[tid] = oi; }
        }
        __syncthreads();
    }
    if (tid == 0) {
        int am = ri[0];
        int sx = am / SH, sy = am - sx * SH;
        float shx = -(float)(sx - MS);
        float shy = -(float)(sy - MS);
        int xm = sx - 1; if (xm < 0) xm += SH;
        int xp = sx + 1; if (xp > SH - 1) xp = SH - 1;
        int ym = sy - 1; if (ym < 0) ym += SH;
        int yp = sy + 1; if (yp > SH - 1) yp = SH - 1;
        float lxm = logf(sncc[xm * SH + sy]);
        float lxp = logf(sncc[xp * SH + sy]);
        float lym = logf(sncc[sx * SH + ym]);
        float lyp = logf(sncc[sx * SH + yp]);
        float lc4 = 4.f * logf(sncc[sx * SH + sy]);
        shx -= (lxm - lxp) / (2.f * lxm - lc4 + 2.f * lxp);
        shy -= (lym - lyp) / (2.f * lym - lc4 + 2.f * lyp);
        g_shift[b * 2 + 0] = shx;
        g_shift[b * 2 + 1] = shy;
    }
}

// ---------------- K5: bilinear warp (constant weights) + transposed store ----------------
__global__ void __launch_bounds__(256) k_warp(const float* __restrict__ fr,
                                              float* __restrict__ out) {
    int b = blockIdx.z;
    int X0 = blockIdx.x * 32, Y0 = blockIdx.y * 32;
    float dy = g_shift[b * 2 + 0];
    float dx = g_shift[b * 2 + 1];
    float fy = floorf(-dy), fx = floorf(-dx);
    int Ay = (int)fy, Ax = (int)fx;
    float wy = -dy - fy, wx = -dx - fx;
    float c00 = (1.f - wy) * (1.f - wx);
    float c01 = (1.f - wy) * wx;
    float c10 = wy * (1.f - wx);
    float c11 = wy * wx;

    __shared__ float sp[33 * 37];
    const float* im = fr + (size_t)b * NPIX;
    for (int idx = threadIdx.x; idx < 33 * 33; idx += 256) {
        int r = idx / 33, c = idx - r * 33;
        int gy = Y0 + Ay + r, gx = X0 + Ax + c;
        float v = (gy >= 0 && gy < HH && gx >= 0 && gx < WW) ? im[gy * WW + gx] : 0.f;
        sp[r * 37 + c] = v;
    }
    __syncthreads();

    int tx = threadIdx.x >> 3;
    int qy = (threadIdx.x & 7) << 2;
    float cA[5], cB[5];
#pragma unroll
    for (int i = 0; i < 5; ++i) {
        cA[i] = sp[(qy + i) * 37 + tx];
        cB[i] = sp[(qy + i) * 37 + tx + 1];
    }
    float4 o;
    o.x = fmaf(c00, cA[0], fmaf(c01, cB[0], fmaf(c10, cA[1], c11 * cB[1])));
    o.y = fmaf(c00, cA[1], fmaf(c01, cB[1], fmaf(c10, cA[2], c11 * cB[2])));
    o.z = fmaf(c00, cA[2], fmaf(c01, cB[2], fmaf(c10, cA[3], c11 * cB[3])));
    o.w = fmaf(c00, cA[3], fmaf(c01, cB[3], fmaf(c10, cA[4], c11 * cB[4])));
    *(float4*)(out + (size_t)b * NPIX + (size_t)(X0 + tx) * HH + Y0 + qy) = o;
}

// ---------------- launch ----------------
extern "C" void kernel_launch(void* const* d_in, const int* in_sizes, int n_in,
                              void* d_out, int out_size) {
    const float* fr = (const float*)d_in[0];
    const float* tp = (const float*)d_in[1];
    if (n_in >= 2 && in_sizes[0] < in_sizes[1]) { const float* t = fr; fr = tp; tp = t; }
    float* out = (float*)d_out;

    cudaFuncSetAttribute(k_corr,  cudaFuncAttributeMaxDynamicSharedMemorySize, SMEM_CORR);
    cudaFuncSetAttribute(k_stats, cudaFuncAttributeMaxDynamicSharedMemorySize, SMEM_STATS);

    k_zero<<<64, 512>>>();
    k_colpart<<<dim3(NB + 1, 8), 512>>>(fr, tp);
    k_stats<<<NB, 512, SMEM_STATS>>>(fr);
    k_corr<<<dim3(NBAND, 8), CTH, SMEM_CORR>>>(fr, tp);
    k_peak<<<NB, 512>>>();
    k_warp<<<dim3(16, 16, NB), 256>>>(fr, out);
}